// round 5
// baseline (speedup 1.0000x reference)
#include <cuda_runtime.h>
#include <math_constants.h>

// Problem constants (fixed shape)
#define BB 8
#define SS 512
#define ROWS (BB * SS)
#define VV 32000
#define V4 (VV / 4)            // 8000 float4 per row
#define EPS_SMOOTH 0.1f
#define REP_W 0.2f
#define IGNORE_IDX (-100)

#define RK_THREADS 512
#define FULL_IT (V4 / RK_THREADS)       // 15
#define REM (V4 - FULL_IT * RK_THREADS) // 320

// Scratch (no allocation allowed -> __device__ globals)
__device__ float g_per_tok[ROWS];
__device__ float g_valid[ROWS];
__device__ int   g_pred[ROWS];
__device__ float g_per_b[BB];
__device__ float g_ce_part[BB];
__device__ float g_val_part[BB];
__device__ int   g_arrive;   // zero-init; reset by last rep_final block

// ---------------- packed f32x2 helpers (Blackwell) ----------------
__device__ __forceinline__ unsigned long long pack2(float a, float b) {
    unsigned long long r;
    asm("mov.b64 %0, {%1, %2};" : "=l"(r) : "f"(a), "f"(b));
    return r;
}
__device__ __forceinline__ void unpack2(unsigned long long p, float& a, float& b) {
    asm("mov.b64 {%0, %1}, %2;" : "=f"(a), "=f"(b) : "l"(p));
}
__device__ __forceinline__ unsigned long long addf2(unsigned long long a, unsigned long long b) {
    unsigned long long r;
    asm("add.rn.f32x2 %0, %1, %2;" : "=l"(r) : "l"(a), "l"(b));
    return r;
}
__device__ __forceinline__ unsigned long long mulf2(unsigned long long a, unsigned long long b) {
    unsigned long long r;
    asm("mul.rn.f32x2 %0, %1, %2;" : "=l"(r) : "l"(a), "l"(b));
    return r;
}
__device__ __forceinline__ float ex2f(float x) {
    float r;
    asm("ex2.approx.f32 %0, %1;" : "=f"(r) : "f"(x));
    return r;
}

// ---------------------------------------------------------------------------
// Kernel 1: one block per row, single branch-free pass over V floats.
//   s = sum(exp(x))  via packed f32x2 scale + MUFU.EX2 + packed adds
//   t = sum(x)       via packed f32x2 adds
//   argmax via index-in-mantissa keys (LOP3 + FMNMX per element)
// Label-width (int64 vs int32) detection is inlined (warp 0, deterministic,
// L2-resident label words), removing the former serial detect kernel.
// ---------------------------------------------------------------------------
__global__ void __launch_bounds__(RK_THREADS) row_kernel(const float* __restrict__ logits,
                                                          const void* __restrict__ labels) {
    const int row = blockIdx.x;
    const float* __restrict__ x = logits + (size_t)row * VV;
    const int tid = threadIdx.x;
    const float4* __restrict__ x4 = (const float4*)x;

    const unsigned long long L2E2 = pack2(1.4426950408889634f, 1.4426950408889634f);

    unsigned long long s01 = 0ull, s23 = 0ull;   // (0.f,0.f) packed
    unsigned long long t01 = 0ull, t23 = 0ull;
    float k0 = -CUDART_INF_F, k1 = -CUDART_INF_F, k2 = -CUDART_INF_F, k3 = -CUDART_INF_F;

    #define BODY(kk, i)                                                         \
        do {                                                                    \
            float4 v = __ldcs(&x4[(i)]);                                        \
            unsigned long long vxy = pack2(v.x, v.y);                           \
            unsigned long long vzw = pack2(v.z, v.w);                           \
            t01 = addf2(t01, vxy);                                              \
            t23 = addf2(t23, vzw);                                              \
            unsigned long long wxy = mulf2(vxy, L2E2);                          \
            unsigned long long wzw = mulf2(vzw, L2E2);                          \
            float w0, w1, w2, w3;                                               \
            unpack2(wxy, w0, w1);                                               \
            unpack2(wzw, w2, w3);                                               \
            float e0 = ex2f(w0), e1 = ex2f(w1), e2 = ex2f(w2), e3 = ex2f(w3);   \
            s01 = addf2(s01, pack2(e0, e1));                                    \
            s23 = addf2(s23, pack2(e2, e3));                                    \
            k0 = fmaxf(k0, __int_as_float((__float_as_int(v.x) & ~15) | (kk))); \
            k1 = fmaxf(k1, __int_as_float((__float_as_int(v.y) & ~15) | (kk))); \
            k2 = fmaxf(k2, __int_as_float((__float_as_int(v.z) & ~15) | (kk))); \
            k3 = fmaxf(k3, __int_as_float((__float_as_int(v.w) & ~15) | (kk))); \
        } while (0)

    #pragma unroll 5
    for (int k = 0; k < FULL_IT; k++) {
        BODY(k, tid + k * RK_THREADS);
    }
    if (tid < REM) {
        BODY(FULL_IT, tid + FULL_IT * RK_THREADS);
    }
    #undef BODY

    // Inline label-width detection (warp 0): check 256 word-pairs of the
    // labels buffer. int64 LE => w[2i+1] == sign-extension(w[2i]). Labels are
    // tiny (<=32KB) and L2-resident; deterministic identical result per block.
    __shared__ int sh_is64;
    if (tid < 32) {
        const int* lw = (const int*)labels;
        bool ok = true;
        #pragma unroll
        for (int kq = 0; kq < 8; kq++) {
            int pi = tid + kq * 32;          // pair index 0..255 (words 0..511, safe both ways)
            int lo = __ldg(&lw[2 * pi]);
            int hi = __ldg(&lw[2 * pi + 1]);
            if (hi != (lo < 0 ? -1 : 0)) ok = false;
        }
        unsigned ball = __ballot_sync(0xffffffffu, ok);
        if (tid == 0) sh_is64 = (ball == 0xffffffffu) ? 1 : 0;
    }

    // Collapse sums
    float sa, sb, sc, sd, ta, tb, tc, td;
    unpack2(s01, sa, sb);
    unpack2(s23, sc, sd);
    unpack2(t01, ta, tb);
    unpack2(t23, tc, td);
    float s = (sa + sb) + (sc + sd);
    float t = (ta + tb) + (tc + td);

    // Pick best slot and decode index
    float bk = k0;
    int bs = 0;
    if (k1 > bk) { bk = k1; bs = 1; }
    if (k2 > bk) { bk = k2; bs = 2; }
    if (k3 > bk) { bk = k3; bs = 3; }
    int kb = __float_as_int(bk);
    int iter = kb & 15;
    float m = __int_as_float(kb & ~15);   // truncated value (consistent across threads)
    int am = (((iter * RK_THREADS) + tid) << 2) + bs;

    // warp reduce (s, t) sums and (m, am) argmax (prefer smaller index on ties)
    #pragma unroll
    for (int off = 16; off; off >>= 1) {
        float s2r = __shfl_down_sync(0xffffffffu, s, off);
        float t2r = __shfl_down_sync(0xffffffffu, t, off);
        float m2r = __shfl_down_sync(0xffffffffu, m, off);
        int   a2r = __shfl_down_sync(0xffffffffu, am, off);
        s += s2r;
        t += t2r;
        if (m2r > m || (m2r == m && a2r < am)) am = a2r;
        m = fmaxf(m, m2r);
    }

    __shared__ float shs[RK_THREADS / 32], sht[RK_THREADS / 32], shm[RK_THREADS / 32];
    __shared__ int   sha[RK_THREADS / 32];
    int wid = tid >> 5;
    if ((tid & 31) == 0) { shs[wid] = s; sht[wid] = t; shm[wid] = m; sha[wid] = am; }
    __syncthreads();

    if (tid == 0) {
        s = shs[0]; t = sht[0]; m = shm[0]; am = sha[0];
        #pragma unroll
        for (int i = 1; i < RK_THREADS / 32; i++) {
            s += shs[i];
            t += sht[i];
            if (shm[i] > m || (shm[i] == m && sha[i] < am)) am = sha[i];
            m = fmaxf(m, shm[i]);
        }
        float lse = logf(s);

        long long lab;
        if (sh_is64) lab = ((const long long*)labels)[row];
        else         lab = (long long)(((const int*)labels)[row]);
        bool valid = (lab != IGNORE_IDX);
        int  li = valid ? (int)lab : 0;
        float xl = __ldg(&x[li]);

        float per = lse - (1.0f - EPS_SMOOTH) * xl - EPS_SMOOTH * (t / (float)VV);
        g_per_tok[row] = valid ? per : 0.f;
        g_valid[row]   = valid ? 1.f : 0.f;
        g_pred[row]    = am;
    }
}

// ---------------------------------------------------------------------------
// Kernel 2 (fused): rep loss per batch + CE partials; last arriving block
// combines everything, writes out[0..2] = (total, ce, rep), resets g_arrive.
// ---------------------------------------------------------------------------
__global__ void __launch_bounds__(512) rep_final_kernel(float* __restrict__ out, int out_size) {
    const int b = blockIdx.x;
    const int i = threadIdx.x;

    __shared__ int   sp[SS];
    __shared__ float sv[SS];
    __shared__ float redA[16];
    __shared__ float redB[16];
    __shared__ float redC[16];

    int row = b * SS + i;
    int   p  = g_pred[row];
    float v  = g_valid[row];
    float pt = g_per_tok[row];
    sp[i] = p;
    sv[i] = v;
    __syncthreads();

    // total valid count + CE partial (sum per_tok)
    float total = v, ces = pt;
    #pragma unroll
    for (int off = 16; off; off >>= 1) {
        total += __shfl_down_sync(0xffffffffu, total, off);
        ces   += __shfl_down_sync(0xffffffffu, ces,   off);
    }
    if ((i & 31) == 0) { redA[i >> 5] = total; redC[i >> 5] = ces; }
    __syncthreads();
    if (i < 16) {
        float xx = redA[i];
        float cc = redC[i];
        #pragma unroll
        for (int off = 8; off; off >>= 1) {
            xx += __shfl_down_sync(0xffffu, xx, off);
            cc += __shfl_down_sync(0xffffu, cc, off);
        }
        if (i == 0) { redA[0] = xx; redC[0] = cc; }
    }
    __syncthreads();
    total = redA[0];
    float ce_sum = redC[0];
    __syncthreads();

    // per-position count + first-occurrence flag (exact unique/counts semantics)
    float c = 0.f;
    bool first = (v > 0.f);
    for (int j = 0; j < SS; j++) {
        bool match = (sp[j] == p) && (sv[j] > 0.f);
        c += match ? 1.f : 0.f;
        if (match && j < i) first = false;
    }

    float ent = 0.f, nu = 0.f;
    if (v > 0.f && first) {
        float pr = c / fmaxf(total, 1.f);
        ent = -pr * logf(pr + 1e-10f);
        nu  = 1.f;
    }

    #pragma unroll
    for (int off = 16; off; off >>= 1) {
        ent += __shfl_down_sync(0xffffffffu, ent, off);
        nu  += __shfl_down_sync(0xffffffffu, nu,  off);
    }
    if ((i & 31) == 0) { redA[i >> 5] = ent; redB[i >> 5] = nu; }
    __syncthreads();
    if (i < 16) {
        float ea = redA[i];
        float na = redB[i];
        #pragma unroll
        for (int off = 8; off; off >>= 1) {
            ea += __shfl_down_sync(0xffffu, ea, off);
            na += __shfl_down_sync(0xffffu, na, off);
        }
        if (i == 0) {
            g_per_b[b]    = (total > 0.f) ? (1.f - ea / logf(na + 1.f)) : 0.f;
            g_ce_part[b]  = ce_sum;
            g_val_part[b] = total;
        }
    }
    __syncthreads();

    if (i == 0) {
        __threadfence();
        int old = atomicAdd(&g_arrive, 1);
        if (old == BB - 1) {
            __threadfence();
            float cen = 0.f, ced = 0.f, rep = 0.f;
            #pragma unroll
            for (int j = 0; j < BB; j++) {
                cen += g_ce_part[j];
                ced += g_val_part[j];
                rep += g_per_b[j];
            }
            float ce = cen / fmaxf(ced, 1.f);
            rep /= (float)BB;
            float tot = ce + REP_W * rep;
            out[0] = tot;
            if (out_size > 1) out[1] = ce;
            if (out_size > 2) out[2] = rep;
            g_arrive = 0;   // replay-safe reset (all blocks already arrived)
        }
    }
}

extern "C" void kernel_launch(void* const* d_in, const int* in_sizes, int n_in,
                              void* d_out, int out_size) {
    const float* logits = (const float*)d_in[0];
    const void*  labels = d_in[1];

    row_kernel<<<ROWS, RK_THREADS>>>(logits, labels);
    rep_final_kernel<<<BB, SS>>>((float*)d_out, out_size);
}

// round 6
// speedup vs baseline: 1.0244x; 1.0244x over previous
#include <cuda_runtime.h>
#include <math_constants.h>

// Problem constants (fixed shape)
#define BB 8
#define SS 512
#define ROWS (BB * SS)
#define VV 32000
#define V4 (VV / 4)            // 8000 float4 per row
#define EPS_SMOOTH 0.1f
#define REP_W 0.2f
#define IGNORE_IDX (-100)

#define RK_THREADS 512
#define FULL_IT (V4 / RK_THREADS)       // 15
#define REM (V4 - FULL_IT * RK_THREADS) // 320

#define SLICES 8                         // rep blocks per batch
#define RB_BLOCKS (BB * SLICES)          // 64
#define ILOC (SS / SLICES)               // 64 i-values per block
#define JCH 8                            // j-chunks per i
#define JLEN (SS / JCH)                  // 64 j per chunk

// Scratch (no allocation allowed -> __device__ globals)
__device__ float g_per_tok[ROWS];
__device__ float g_valid[ROWS];
__device__ int   g_pred[ROWS];
__device__ float g_ent_part[RB_BLOCKS];
__device__ float g_nu_part[RB_BLOCKS];
__device__ float g_pt_part[RB_BLOCKS];
__device__ float g_v_part[RB_BLOCKS];
__device__ float g_tot_b[BB];
__device__ int   g_arrive;   // zero-init; reset by last rep block each replay

// ---------------- packed f32x2 helpers (Blackwell) ----------------
__device__ __forceinline__ unsigned long long pack2(float a, float b) {
    unsigned long long r;
    asm("mov.b64 %0, {%1, %2};" : "=l"(r) : "f"(a), "f"(b));
    return r;
}
__device__ __forceinline__ void unpack2(unsigned long long p, float& a, float& b) {
    asm("mov.b64 {%0, %1}, %2;" : "=f"(a), "=f"(b) : "l"(p));
}
__device__ __forceinline__ unsigned long long addf2(unsigned long long a, unsigned long long b) {
    unsigned long long r;
    asm("add.rn.f32x2 %0, %1, %2;" : "=l"(r) : "l"(a), "l"(b));
    return r;
}
__device__ __forceinline__ unsigned long long mulf2(unsigned long long a, unsigned long long b) {
    unsigned long long r;
    asm("mul.rn.f32x2 %0, %1, %2;" : "=l"(r) : "l"(a), "l"(b));
    return r;
}
__device__ __forceinline__ float ex2f(float x) {
    float r;
    asm("ex2.approx.f32 %0, %1;" : "=f"(r) : "f"(x));
    return r;
}

// ---------------------------------------------------------------------------
// Kernel 1: one block per row, single branch-free pass over V floats.
// (plain LDG.128 loads — __ldcs measured +13us regression, reverted)
// ---------------------------------------------------------------------------
__global__ void __launch_bounds__(RK_THREADS) row_kernel(const float* __restrict__ logits,
                                                          const void* __restrict__ labels) {
    const int row = blockIdx.x;
    const float* __restrict__ x = logits + (size_t)row * VV;
    const int tid = threadIdx.x;
    const float4* __restrict__ x4 = (const float4*)x;

    const unsigned long long L2E2 = pack2(1.4426950408889634f, 1.4426950408889634f);

    unsigned long long s01 = 0ull, s23 = 0ull;
    unsigned long long t01 = 0ull, t23 = 0ull;
    float k0 = -CUDART_INF_F, k1 = -CUDART_INF_F, k2 = -CUDART_INF_F, k3 = -CUDART_INF_F;

    #define BODY(kk, i)                                                         \
        do {                                                                    \
            float4 v = x4[(i)];                                                 \
            unsigned long long vxy = pack2(v.x, v.y);                           \
            unsigned long long vzw = pack2(v.z, v.w);                           \
            t01 = addf2(t01, vxy);                                              \
            t23 = addf2(t23, vzw);                                              \
            unsigned long long wxy = mulf2(vxy, L2E2);                          \
            unsigned long long wzw = mulf2(vzw, L2E2);                          \
            float w0, w1, w2, w3;                                               \
            unpack2(wxy, w0, w1);                                               \
            unpack2(wzw, w2, w3);                                               \
            float e0 = ex2f(w0), e1 = ex2f(w1), e2 = ex2f(w2), e3 = ex2f(w3);   \
            s01 = addf2(s01, pack2(e0, e1));                                    \
            s23 = addf2(s23, pack2(e2, e3));                                    \
            k0 = fmaxf(k0, __int_as_float((__float_as_int(v.x) & ~15) | (kk))); \
            k1 = fmaxf(k1, __int_as_float((__float_as_int(v.y) & ~15) | (kk))); \
            k2 = fmaxf(k2, __int_as_float((__float_as_int(v.z) & ~15) | (kk))); \
            k3 = fmaxf(k3, __int_as_float((__float_as_int(v.w) & ~15) | (kk))); \
        } while (0)

    #pragma unroll 5
    for (int k = 0; k < FULL_IT; k++) {
        BODY(k, tid + k * RK_THREADS);
    }
    if (tid < REM) {
        BODY(FULL_IT, tid + FULL_IT * RK_THREADS);
    }
    #undef BODY

    // Inline label-width detection (warp 0): int64 LE => w[2i+1]==signext(w[2i]).
    __shared__ int sh_is64;
    if (tid < 32) {
        const int* lw = (const int*)labels;
        bool ok = true;
        #pragma unroll
        for (int kq = 0; kq < 8; kq++) {
            int pi = tid + kq * 32;
            int lo = __ldg(&lw[2 * pi]);
            int hi = __ldg(&lw[2 * pi + 1]);
            if (hi != (lo < 0 ? -1 : 0)) ok = false;
        }
        unsigned ball = __ballot_sync(0xffffffffu, ok);
        if (tid == 0) sh_is64 = (ball == 0xffffffffu) ? 1 : 0;
    }

    float sa, sb, sc, sd, ta, tb, tc, td;
    unpack2(s01, sa, sb);
    unpack2(s23, sc, sd);
    unpack2(t01, ta, tb);
    unpack2(t23, tc, td);
    float s = (sa + sb) + (sc + sd);
    float t = (ta + tb) + (tc + td);

    float bk = k0;
    int bs = 0;
    if (k1 > bk) { bk = k1; bs = 1; }
    if (k2 > bk) { bk = k2; bs = 2; }
    if (k3 > bk) { bk = k3; bs = 3; }
    int kb = __float_as_int(bk);
    int iter = kb & 15;
    float m = __int_as_float(kb & ~15);
    int am = (((iter * RK_THREADS) + tid) << 2) + bs;

    #pragma unroll
    for (int off = 16; off; off >>= 1) {
        float s2r = __shfl_down_sync(0xffffffffu, s, off);
        float t2r = __shfl_down_sync(0xffffffffu, t, off);
        float m2r = __shfl_down_sync(0xffffffffu, m, off);
        int   a2r = __shfl_down_sync(0xffffffffu, am, off);
        s += s2r;
        t += t2r;
        if (m2r > m || (m2r == m && a2r < am)) am = a2r;
        m = fmaxf(m, m2r);
    }

    __shared__ float shs[RK_THREADS / 32], sht[RK_THREADS / 32], shm[RK_THREADS / 32];
    __shared__ int   sha[RK_THREADS / 32];
    int wid = tid >> 5;
    if ((tid & 31) == 0) { shs[wid] = s; sht[wid] = t; shm[wid] = m; sha[wid] = am; }
    __syncthreads();

    if (tid == 0) {
        s = shs[0]; t = sht[0]; m = shm[0]; am = sha[0];
        #pragma unroll
        for (int i = 1; i < RK_THREADS / 32; i++) {
            s += shs[i];
            t += sht[i];
            if (shm[i] > m || (shm[i] == m && sha[i] < am)) am = sha[i];
            m = fmaxf(m, shm[i]);
        }
        float lse = logf(s);

        long long lab;
        if (sh_is64) lab = ((const long long*)labels)[row];
        else         lab = (long long)(((const int*)labels)[row]);
        bool valid = (lab != IGNORE_IDX);
        int  li = valid ? (int)lab : 0;
        float xl = __ldg(&x[li]);

        float per = lse - (1.0f - EPS_SMOOTH) * xl - EPS_SMOOTH * (t / (float)VV);
        g_per_tok[row] = valid ? per : 0.f;
        g_valid[row]   = valid ? 1.f : 0.f;
        g_pred[row]    = am;
    }
}

// ---------------------------------------------------------------------------
// Kernel 2: rep loss spread over 64 blocks (8 slices per batch) + CE partials.
// Thread t: i_local = t>>3, j_chunk = t&7. Each thread scans 64 j's; the 8
// chunk-threads for one i combine via shfl_xor (aligned groups of 8).
// Last arriving block combines all partials IN FIXED ORDER (deterministic).
// ---------------------------------------------------------------------------
__global__ void __launch_bounds__(512) rep_kernel(float* __restrict__ out, int out_size) {
    const int g  = blockIdx.x;
    const int b  = g >> 3;          // batch
    const int sl = g & 7;           // slice
    const int t  = threadIdx.x;
    const int il = t >> 3;          // i_local 0..63
    const int ch = t & 7;           // j chunk 0..7
    const int i  = sl * ILOC + il;  // global i within batch

    __shared__ int   sp[SS];
    __shared__ float sv[SS];
    __shared__ float red1[16], red2[16], red3[16], red4[16];

    // load full batch preds/valid
    {
        int row = b * SS + t;
        sp[t] = g_pred[row];
        sv[t] = g_valid[row];
    }
    __syncthreads();

    // total valid for this batch (redundant per block; deterministic)
    float total = sv[t];
    #pragma unroll
    for (int off = 16; off; off >>= 1) total += __shfl_down_sync(0xffffffffu, total, off);
    if ((t & 31) == 0) red1[t >> 5] = total;
    __syncthreads();
    if (t < 16) {
        float xx = red1[t];
        #pragma unroll
        for (int off = 8; off; off >>= 1) xx += __shfl_down_sync(0xffffu, xx, off);
        if (t == 0) red1[0] = xx;
    }
    __syncthreads();
    total = red1[0];
    __syncthreads();

    // partial count + any-earlier-match over this thread's 64 j's
    int   p  = sp[i];
    float vi = sv[i];
    float c = 0.f;
    int lt = 0;
    int j0 = ch * JLEN;
    #pragma unroll 8
    for (int jj = 0; jj < JLEN; jj++) {
        int j = j0 + jj;
        bool match = (sp[j] == p) && (sv[j] > 0.f);
        c += match ? 1.f : 0.f;
        lt |= (match && (j < i)) ? 1 : 0;
    }
    // combine across the 8 aligned chunk-threads
    #pragma unroll
    for (int off = 1; off < 8; off <<= 1) {
        c  += __shfl_xor_sync(0xffffffffu, c,  off);
        lt |= __shfl_xor_sync(0xffffffffu, lt, off);
    }

    // first-occurrence entropy contribution (count once: chunk 0 only)
    float ent = 0.f, nu = 0.f, pts = 0.f, vls = 0.f;
    if (ch == 0) {
        bool first = (vi > 0.f) && !lt;
        if (first) {
            float pr = c / fmaxf(total, 1.f);
            ent = -pr * logf(pr + 1e-10f);
            nu  = 1.f;
        }
        int row = b * SS + i;
        pts = g_per_tok[row];   // CE partial over this block's 64 rows
        vls = vi;
    }

    // block reduce (ent, nu, pts, vls)
    #pragma unroll
    for (int off = 16; off; off >>= 1) {
        ent += __shfl_down_sync(0xffffffffu, ent, off);
        nu  += __shfl_down_sync(0xffffffffu, nu,  off);
        pts += __shfl_down_sync(0xffffffffu, pts, off);
        vls += __shfl_down_sync(0xffffffffu, vls, off);
    }
    if ((t & 31) == 0) { red1[t >> 5] = ent; red2[t >> 5] = nu; red3[t >> 5] = pts; red4[t >> 5] = vls; }
    __syncthreads();
    if (t < 16) {
        float e = red1[t], n = red2[t], q = red3[t], w = red4[t];
        #pragma unroll
        for (int off = 8; off; off >>= 1) {
            e += __shfl_down_sync(0xffffu, e, off);
            n += __shfl_down_sync(0xffffu, n, off);
            q += __shfl_down_sync(0xffffu, q, off);
            w += __shfl_down_sync(0xffffu, w, off);
        }
        if (t == 0) {
            g_ent_part[g] = e;
            g_nu_part[g]  = n;
            g_pt_part[g]  = q;
            g_v_part[g]   = w;
            if (sl == 0) g_tot_b[b] = total;
        }
    }
    __syncthreads();

    if (t == 0) {
        __threadfence();
        int old = atomicAdd(&g_arrive, 1);
        if (old == RB_BLOCKS - 1) {
            __threadfence();
            float rep = 0.f;
            #pragma unroll
            for (int bb = 0; bb < BB; bb++) {
                float eb = 0.f, nb = 0.f;
                #pragma unroll
                for (int ss2 = 0; ss2 < SLICES; ss2++) {
                    eb += g_ent_part[bb * SLICES + ss2];
                    nb += g_nu_part[bb * SLICES + ss2];
                }
                float tb2 = g_tot_b[bb];
                rep += (tb2 > 0.f) ? (1.f - eb / logf(nb + 1.f)) : 0.f;
            }
            rep /= (float)BB;
            float cen = 0.f, ced = 0.f;
            #pragma unroll
            for (int jq = 0; jq < RB_BLOCKS; jq++) {
                cen += g_pt_part[jq];
                ced += g_v_part[jq];
            }
            float ce = cen / fmaxf(ced, 1.f);
            float tot = ce + REP_W * rep;
            out[0] = tot;
            if (out_size > 1) out[1] = ce;
            if (out_size > 2) out[2] = rep;
            g_arrive = 0;   // replay-safe reset
        }
    }
}

extern "C" void kernel_launch(void* const* d_in, const int* in_sizes, int n_in,
                              void* d_out, int out_size) {
    const float* logits = (const float*)d_in[0];
    const void*  labels = d_in[1];

    row_kernel<<<ROWS, RK_THREADS>>>(logits, labels);
    rep_kernel<<<RB_BLOCKS, 512>>>((float*)d_out, out_size);
}

// round 7
// speedup vs baseline: 1.1047x; 1.0785x over previous
#include <cuda_runtime.h>
#include <math_constants.h>

// Problem constants (fixed shape)
#define BB 8
#define SS 512
#define ROWS (BB * SS)
#define VV 32000
#define V4 (VV / 4)            // 8000 float4 per row
#define EPS_SMOOTH 0.1f
#define REP_W 0.2f
#define IGNORE_IDX (-100)

#define RK_THREADS 512
#define FULL_IT (V4 / RK_THREADS)       // 15
#define REM (V4 - FULL_IT * RK_THREADS) // 320

#define GRID 296                         // 2 blocks/SM x 148 SMs, all resident
#define SLICES 8                         // rep slices per batch
#define RB_BLOCKS (BB * SLICES)          // 64 rep blocks
#define ILOC (SS / SLICES)               // 64 i-values per rep block
#define JLEN (SS / 8)                    // 64 j per chunk-thread

// Scratch (no allocation allowed -> __device__ globals; zero-init, counters
// reset by the final block each replay)
__device__ float g_per_tok[ROWS];
__device__ float g_valid[ROWS];
__device__ int   g_pred[ROWS];
__device__ float g_ent_part[RB_BLOCKS];
__device__ float g_nu_part[RB_BLOCKS];
__device__ float g_pt_part[RB_BLOCKS];
__device__ float g_v_part[RB_BLOCKS];
__device__ float g_tot_b[BB];
__device__ int   g_arrive;
__device__ int   g_arrive2;

// ---------------- packed f32x2 helpers (Blackwell) ----------------
__device__ __forceinline__ unsigned long long pack2(float a, float b) {
    unsigned long long r;
    asm("mov.b64 %0, {%1, %2};" : "=l"(r) : "f"(a), "f"(b));
    return r;
}
__device__ __forceinline__ void unpack2(unsigned long long p, float& a, float& b) {
    asm("mov.b64 {%0, %1}, %2;" : "=f"(a), "=f"(b) : "l"(p));
}
__device__ __forceinline__ unsigned long long addf2(unsigned long long a, unsigned long long b) {
    unsigned long long r;
    asm("add.rn.f32x2 %0, %1, %2;" : "=l"(r) : "l"(a), "l"(b));
    return r;
}
__device__ __forceinline__ unsigned long long mulf2(unsigned long long a, unsigned long long b) {
    unsigned long long r;
    asm("mul.rn.f32x2 %0, %1, %2;" : "=l"(r) : "l"(a), "l"(b));
    return r;
}
__device__ __forceinline__ float ex2f(float x) {
    float r;
    asm("ex2.approx.f32 %0, %1;" : "=f"(r) : "f"(x));
    return r;
}
__device__ __forceinline__ int ld_acquire(int* p) {
    int v;
    asm volatile("ld.global.acquire.gpu.b32 %0, [%1];" : "=r"(v) : "l"(p));
    return v;
}

// ---------------------------------------------------------------------------
// Single persistent fused kernel.
// Phase A (all 296 blocks): strided rows, one-pass exp-sum / sum / argmax.
// Grid barrier (arrive counter + acquire-spin; all blocks resident).
// Phase B (blocks 0..63): rep-loss slices + CE partials; last block combines
// in fixed order, writes out[0..2], resets counters.
// ---------------------------------------------------------------------------
__global__ void __launch_bounds__(RK_THREADS, 2)
fused_kernel(const float* __restrict__ logits, const void* __restrict__ labels,
             float* __restrict__ out, int out_size) {
    const int tid = threadIdx.x;
    const int bid = blockIdx.x;

    __shared__ float shs[RK_THREADS / 32], sht[RK_THREADS / 32], shm[RK_THREADS / 32];
    __shared__ int   sha[RK_THREADS / 32];
    __shared__ int   sh_is64;

    // ---- label width detect ONCE per block, issued FIRST so the latency
    //      hides under the first row's logits loads ----
    if (tid < 32) {
        const int* lw = (const int*)labels;
        bool ok = true;
        #pragma unroll
        for (int kq = 0; kq < 8; kq++) {
            int pi = tid + kq * 32;      // word pairs 0..255 (safe both widths)
            int lo = __ldg(&lw[2 * pi]);
            int hi = __ldg(&lw[2 * pi + 1]);
            if (hi != (lo < 0 ? -1 : 0)) ok = false;
        }
        unsigned ball = __ballot_sync(0xffffffffu, ok);
        if (tid == 0) sh_is64 = (ball == 0xffffffffu) ? 1 : 0;
    }

    const unsigned long long L2E2 = pack2(1.4426950408889634f, 1.4426950408889634f);

    // ---------------- Phase A: rows ----------------
    for (int row = bid; row < ROWS; row += GRID) {
        const float4* __restrict__ x4 = (const float4*)(logits + (size_t)row * VV);

        unsigned long long s01 = 0ull, s23 = 0ull;
        unsigned long long t01 = 0ull, t23 = 0ull;
        float k0 = -CUDART_INF_F, k1 = -CUDART_INF_F, k2 = -CUDART_INF_F, k3 = -CUDART_INF_F;

        #define BODY(kk, i)                                                         \
            do {                                                                    \
                float4 v = x4[(i)];                                                 \
                unsigned long long vxy = pack2(v.x, v.y);                           \
                unsigned long long vzw = pack2(v.z, v.w);                           \
                t01 = addf2(t01, vxy);                                              \
                t23 = addf2(t23, vzw);                                              \
                unsigned long long wxy = mulf2(vxy, L2E2);                          \
                unsigned long long wzw = mulf2(vzw, L2E2);                          \
                float w0, w1, w2, w3;                                               \
                unpack2(wxy, w0, w1);                                               \
                unpack2(wzw, w2, w3);                                               \
                float e0 = ex2f(w0), e1 = ex2f(w1), e2 = ex2f(w2), e3 = ex2f(w3);   \
                s01 = addf2(s01, pack2(e0, e1));                                    \
                s23 = addf2(s23, pack2(e2, e3));                                    \
                k0 = fmaxf(k0, __int_as_float((__float_as_int(v.x) & ~15) | (kk))); \
                k1 = fmaxf(k1, __int_as_float((__float_as_int(v.y) & ~15) | (kk))); \
                k2 = fmaxf(k2, __int_as_float((__float_as_int(v.z) & ~15) | (kk))); \
                k3 = fmaxf(k3, __int_as_float((__float_as_int(v.w) & ~15) | (kk))); \
            } while (0)

        #pragma unroll 5
        for (int k = 0; k < FULL_IT; k++) {
            BODY(k, tid + k * RK_THREADS);
        }
        if (tid < REM) {
            BODY(FULL_IT, tid + FULL_IT * RK_THREADS);
        }
        #undef BODY

        float sa, sb, sc, sd, ta, tb, tc, td;
        unpack2(s01, sa, sb);
        unpack2(s23, sc, sd);
        unpack2(t01, ta, tb);
        unpack2(t23, tc, td);
        float s = (sa + sb) + (sc + sd);
        float t = (ta + tb) + (tc + td);

        float bk = k0;
        int bs = 0;
        if (k1 > bk) { bk = k1; bs = 1; }
        if (k2 > bk) { bk = k2; bs = 2; }
        if (k3 > bk) { bk = k3; bs = 3; }
        int kb = __float_as_int(bk);
        int iter = kb & 15;
        float m = __int_as_float(kb & ~15);
        int am = (((iter * RK_THREADS) + tid) << 2) + bs;

        #pragma unroll
        for (int off = 16; off; off >>= 1) {
            float s2r = __shfl_down_sync(0xffffffffu, s, off);
            float t2r = __shfl_down_sync(0xffffffffu, t, off);
            float m2r = __shfl_down_sync(0xffffffffu, m, off);
            int   a2r = __shfl_down_sync(0xffffffffu, am, off);
            s += s2r;
            t += t2r;
            if (m2r > m || (m2r == m && a2r < am)) am = a2r;
            m = fmaxf(m, m2r);
        }

        int wid = tid >> 5;
        if ((tid & 31) == 0) { shs[wid] = s; sht[wid] = t; shm[wid] = m; sha[wid] = am; }
        __syncthreads();

        if (tid == 0) {
            s = shs[0]; t = sht[0]; m = shm[0]; am = sha[0];
            #pragma unroll
            for (int i = 1; i < RK_THREADS / 32; i++) {
                s += shs[i];
                t += sht[i];
                if (shm[i] > m || (shm[i] == m && sha[i] < am)) am = sha[i];
                m = fmaxf(m, shm[i]);
            }
            float lse = logf(s);

            long long lab;
            if (sh_is64) lab = ((const long long*)labels)[row];
            else         lab = (long long)(((const int*)labels)[row]);
            bool valid = (lab != IGNORE_IDX);
            int  li = valid ? (int)lab : 0;
            float xl = __ldg(&((const float*)(logits + (size_t)row * VV))[li]);

            float per = lse - (1.0f - EPS_SMOOTH) * xl - EPS_SMOOTH * (t / (float)VV);
            g_per_tok[row] = valid ? per : 0.f;
            g_valid[row]   = valid ? 1.f : 0.f;
            g_pred[row]    = am;
        }
        __syncthreads();
    }

    // ---------------- grid barrier ----------------
    __threadfence();
    __syncthreads();
    if (tid == 0) atomicAdd(&g_arrive, 1);

    if (bid >= RB_BLOCKS) return;   // only 64 blocks continue

    if (tid == 0) {
        while (ld_acquire(&g_arrive) < GRID) __nanosleep(64);
    }
    __syncthreads();
    __threadfence();

    // ---------------- Phase B: rep loss ----------------
    const int b  = bid >> 3;        // batch
    const int sl = bid & 7;         // slice
    const int il = tid >> 3;        // i_local 0..63
    const int ch = tid & 7;         // j chunk 0..7
    const int i  = sl * ILOC + il;  // i within batch

    __shared__ int   sp[SS];
    __shared__ float sv[SS];
    __shared__ float red1[16], red2[16], red3[16], red4[16];

    {
        int row = b * SS + tid;
        sp[tid] = g_pred[row];
        sv[tid] = g_valid[row];
    }
    __syncthreads();

    // total valid for batch
    float total = sv[tid];
    #pragma unroll
    for (int off = 16; off; off >>= 1) total += __shfl_down_sync(0xffffffffu, total, off);
    if ((tid & 31) == 0) red1[tid >> 5] = total;
    __syncthreads();
    if (tid < 16) {
        float xx = red1[tid];
        #pragma unroll
        for (int off = 8; off; off >>= 1) xx += __shfl_down_sync(0xffffu, xx, off);
        if (tid == 0) red1[0] = xx;
    }
    __syncthreads();
    total = red1[0];
    __syncthreads();

    // per-i count + any-earlier-match; j strided by 8 (bank-conflict-free:
    // for fixed jj a warp touches 8 consecutive-ish distinct words)
    int   p  = sp[i];
    float vi = sv[i];
    float c = 0.f;
    int lt = 0;
    #pragma unroll 8
    for (int jj = 0; jj < JLEN; jj++) {
        int j = ch + (jj << 3);
        bool match = (sp[j] == p) && (sv[j] > 0.f);
        c += match ? 1.f : 0.f;
        lt |= (match && (j < i)) ? 1 : 0;
    }
    #pragma unroll
    for (int off = 1; off < 8; off <<= 1) {
        c  += __shfl_xor_sync(0xffffffffu, c,  off);
        lt |= __shfl_xor_sync(0xffffffffu, lt, off);
    }

    float ent = 0.f, nu = 0.f, pts = 0.f, vls = 0.f;
    if (ch == 0) {
        bool first = (vi > 0.f) && !lt;
        if (first) {
            float pr = c / fmaxf(total, 1.f);
            ent = -pr * logf(pr + 1e-10f);
            nu  = 1.f;
        }
        int row = b * SS + i;
        pts = g_per_tok[row];
        vls = vi;
    }

    #pragma unroll
    for (int off = 16; off; off >>= 1) {
        ent += __shfl_down_sync(0xffffffffu, ent, off);
        nu  += __shfl_down_sync(0xffffffffu, nu,  off);
        pts += __shfl_down_sync(0xffffffffu, pts, off);
        vls += __shfl_down_sync(0xffffffffu, vls, off);
    }
    if ((tid & 31) == 0) { red1[tid >> 5] = ent; red2[tid >> 5] = nu; red3[tid >> 5] = pts; red4[tid >> 5] = vls; }
    __syncthreads();
    if (tid < 16) {
        float e = red1[tid], n = red2[tid], q = red3[tid], w = red4[tid];
        #pragma unroll
        for (int off = 8; off; off >>= 1) {
            e += __shfl_down_sync(0xffffu, e, off);
            n += __shfl_down_sync(0xffffu, n, off);
            q += __shfl_down_sync(0xffffu, q, off);
            w += __shfl_down_sync(0xffffu, w, off);
        }
        if (tid == 0) {
            g_ent_part[bid] = e;
            g_nu_part[bid]  = n;
            g_pt_part[bid]  = q;
            g_v_part[bid]   = w;
            if (sl == 0) g_tot_b[b] = total;
        }
    }
    __syncthreads();

    if (tid == 0) {
        __threadfence();
        int old = atomicAdd(&g_arrive2, 1);
        if (old == RB_BLOCKS - 1) {
            __threadfence();
            float rep = 0.f;
            #pragma unroll
            for (int bb = 0; bb < BB; bb++) {
                float eb = 0.f, nb = 0.f;
                #pragma unroll
                for (int ss2 = 0; ss2 < SLICES; ss2++) {
                    eb += g_ent_part[bb * SLICES + ss2];
                    nb += g_nu_part[bb * SLICES + ss2];
                }
                float tb2 = g_tot_b[bb];
                rep += (tb2 > 0.f) ? (1.f - eb / logf(nb + 1.f)) : 0.f;
            }
            rep /= (float)BB;
            float cen = 0.f, ced = 0.f;
            #pragma unroll
            for (int jq = 0; jq < RB_BLOCKS; jq++) {
                cen += g_pt_part[jq];
                ced += g_v_part[jq];
            }
            float ce = cen / fmaxf(ced, 1.f);
            float tot = ce + REP_W * rep;
            out[0] = tot;
            if (out_size > 1) out[1] = ce;
            if (out_size > 2) out[2] = rep;
            g_arrive  = 0;   // replay-safe resets (everyone already passed)
            g_arrive2 = 0;
        }
    }
}

extern "C" void kernel_launch(void* const* d_in, const int* in_sizes, int n_in,
                              void* d_out, int out_size) {
    const float* logits = (const float*)d_in[0];
    const void*  labels = d_in[1];

    fused_kernel<<<GRID, RK_THREADS>>>(logits, labels, (float*)d_out, out_size);
}

// round 8
// speedup vs baseline: 1.1272x; 1.0203x over previous
#include <cuda_runtime.h>
#include <math_constants.h>

// Problem constants (fixed shape)
#define BB 8
#define SS 512
#define ROWS (BB * SS)
#define VV 32000
#define V4 (VV / 4)            // 8000 float4 per row
#define EPS_SMOOTH 0.1f
#define REP_W 0.2f
#define IGNORE_IDX (-100)

#define RK_THREADS 512
#define FULL_IT (V4 / RK_THREADS)       // 15
#define REM (V4 - FULL_IT * RK_THREADS) // 320

#define GRID 296                         // 2 blocks/SM x 148 SMs, all resident
#define SLICES 8
#define RB_BLOCKS (BB * SLICES)          // 64
#define ILOC (SS / SLICES)               // 64
#define JLEN (SS / 8)                    // 64

// Scratch (no allocation allowed -> __device__ globals)
__device__ float g_per_tok[ROWS];
__device__ float g_valid[ROWS];
__device__ int   g_pred[ROWS];
__device__ float g_ent_part[RB_BLOCKS];
__device__ float g_nu_part[RB_BLOCKS];
__device__ float g_pt_part[RB_BLOCKS];
__device__ float g_v_part[RB_BLOCKS];
__device__ float g_tot_b[BB];
__device__ int   g_arrive;
__device__ int   g_arrive2;

// ---------------- packed f32x2 helpers (Blackwell) ----------------
__device__ __forceinline__ unsigned long long pack2(float a, float b) {
    unsigned long long r;
    asm("mov.b64 %0, {%1, %2};" : "=l"(r) : "f"(a), "f"(b));
    return r;
}
__device__ __forceinline__ void unpack2(unsigned long long p, float& a, float& b) {
    asm("mov.b64 {%0, %1}, %2;" : "=f"(a), "=f"(b) : "l"(p));
}
__device__ __forceinline__ unsigned long long addf2(unsigned long long a, unsigned long long b) {
    unsigned long long r;
    asm("add.rn.f32x2 %0, %1, %2;" : "=l"(r) : "l"(a), "l"(b));
    return r;
}
__device__ __forceinline__ unsigned long long mulf2(unsigned long long a, unsigned long long b) {
    unsigned long long r;
    asm("mul.rn.f32x2 %0, %1, %2;" : "=l"(r) : "l"(a), "l"(b));
    return r;
}
__device__ __forceinline__ float ex2f(float x) {
    float r;
    asm("ex2.approx.f32 %0, %1;" : "=f"(r) : "f"(x));
    return r;
}
__device__ __forceinline__ int ld_acquire(int* p) {
    int v;
    asm volatile("ld.global.acquire.gpu.b32 %0, [%1];" : "=r"(v) : "l"(p));
    return v;
}

// ---------------------------------------------------------------------------
// Single persistent fused kernel.
// Phase A: strided rows; per-row epilogue off the critical path
//   (label + x[label] prefetched at row start; parity double-buffered
//    reduction scratch removes the trailing barrier; warp-0 shfl-tree merge).
// Grid barrier, then Phase B (blocks 0..63): rep loss + CE partials; last
// block combines in fixed order, writes out, resets counters (replay-safe).
// ---------------------------------------------------------------------------
__global__ void __launch_bounds__(RK_THREADS, 2)
fused_kernel(const float* __restrict__ logits, const void* __restrict__ labels,
             float* __restrict__ out, int out_size) {
    const int tid = threadIdx.x;
    const int bid = blockIdx.x;

    __shared__ float shs[2][16], sht[2][16], shm[2][16];
    __shared__ int   sha[2][16];

    // ---- label width detect: warp 0 only, result stays in registers ----
    int is64 = 0;
    if (tid < 32) {
        const int* lw = (const int*)labels;
        bool ok = true;
        #pragma unroll
        for (int kq = 0; kq < 8; kq++) {
            int pi = tid + kq * 32;
            int lo = __ldg(&lw[2 * pi]);
            int hi = __ldg(&lw[2 * pi + 1]);
            if (hi != (lo < 0 ? -1 : 0)) ok = false;
        }
        unsigned ball = __ballot_sync(0xffffffffu, ok);
        is64 = (ball == 0xffffffffu) ? 1 : 0;
    }

    const unsigned long long L2E2 = pack2(1.4426950408889634f, 1.4426950408889634f);

    // ---------------- Phase A: rows ----------------
    int par = 0;
    for (int row = bid; row < ROWS; row += GRID, par ^= 1) {
        const float* __restrict__ x = logits + (size_t)row * VV;
        const float4* __restrict__ x4 = (const float4*)x;

        // Early prefetch (lane 0 of warp 0 only): label -> x[label].
        // Both loads issue now and resolve during the ~1.7us row stream.
        long long lab = 0;
        float xl = 0.f;
        if (tid == 0) {
            if (is64) lab = ((const long long*)labels)[row];
            else      lab = (long long)(((const int*)labels)[row]);
            int li = (lab != IGNORE_IDX) ? (int)lab : 0;
            xl = __ldg(&x[li]);
        }

        unsigned long long s01 = 0ull, s23 = 0ull;
        unsigned long long t01 = 0ull, t23 = 0ull;
        float k0 = -CUDART_INF_F, k1 = -CUDART_INF_F, k2 = -CUDART_INF_F, k3 = -CUDART_INF_F;

        #define BODY(kk, i)                                                         \
            do {                                                                    \
                float4 v = x4[(i)];                                                 \
                unsigned long long vxy = pack2(v.x, v.y);                           \
                unsigned long long vzw = pack2(v.z, v.w);                           \
                t01 = addf2(t01, vxy);                                              \
                t23 = addf2(t23, vzw);                                              \
                unsigned long long wxy = mulf2(vxy, L2E2);                          \
                unsigned long long wzw = mulf2(vzw, L2E2);                          \
                float w0, w1, w2, w3;                                               \
                unpack2(wxy, w0, w1);                                               \
                unpack2(wzw, w2, w3);                                               \
                float e0 = ex2f(w0), e1 = ex2f(w1), e2 = ex2f(w2), e3 = ex2f(w3);   \
                s01 = addf2(s01, pack2(e0, e1));                                    \
                s23 = addf2(s23, pack2(e2, e3));                                    \
                k0 = fmaxf(k0, __int_as_float((__float_as_int(v.x) & ~15) | (kk))); \
                k1 = fmaxf(k1, __int_as_float((__float_as_int(v.y) & ~15) | (kk))); \
                k2 = fmaxf(k2, __int_as_float((__float_as_int(v.z) & ~15) | (kk))); \
                k3 = fmaxf(k3, __int_as_float((__float_as_int(v.w) & ~15) | (kk))); \
            } while (0)

        #pragma unroll 5
        for (int k = 0; k < FULL_IT; k++) {
            BODY(k, tid + k * RK_THREADS);
        }
        if (tid < REM) {
            BODY(FULL_IT, tid + FULL_IT * RK_THREADS);
        }
        #undef BODY

        float sa, sb, sc, sd, ta, tb, tc, td;
        unpack2(s01, sa, sb);
        unpack2(s23, sc, sd);
        unpack2(t01, ta, tb);
        unpack2(t23, tc, td);
        float s = (sa + sb) + (sc + sd);
        float t = (ta + tb) + (tc + td);

        float bk = k0;
        int bs = 0;
        if (k1 > bk) { bk = k1; bs = 1; }
        if (k2 > bk) { bk = k2; bs = 2; }
        if (k3 > bk) { bk = k3; bs = 3; }
        int kb = __float_as_int(bk);
        int iter = kb & 15;
        float m = __int_as_float(kb & ~15);
        int am = (((iter * RK_THREADS) + tid) << 2) + bs;

        #pragma unroll
        for (int off = 16; off; off >>= 1) {
            float s2r = __shfl_down_sync(0xffffffffu, s, off);
            float t2r = __shfl_down_sync(0xffffffffu, t, off);
            float m2r = __shfl_down_sync(0xffffffffu, m, off);
            int   a2r = __shfl_down_sync(0xffffffffu, am, off);
            s += s2r;
            t += t2r;
            if (m2r > m || (m2r == m && a2r < am)) am = a2r;
            m = fmaxf(m, m2r);
        }

        int wid = tid >> 5;
        if ((tid & 31) == 0) { shs[par][wid] = s; sht[par][wid] = t; shm[par][wid] = m; sha[par][wid] = am; }
        __syncthreads();
        // NOTE: no trailing barrier. Next row writes the other parity set; the
        // row-after-next's writes are ordered behind the next row's barrier,
        // by which time warp 0 has finished this epilogue.

        if (tid < 32) {
            float es = 0.f, et = 0.f, em = -CUDART_INF_F;
            int   ea = 0x7fffffff;
            if (tid < 16) { es = shs[par][tid]; et = sht[par][tid]; em = shm[par][tid]; ea = sha[par][tid]; }
            #pragma unroll
            for (int off = 8; off; off >>= 1) {
                float s2r = __shfl_down_sync(0xffffffffu, es, off);
                float t2r = __shfl_down_sync(0xffffffffu, et, off);
                float m2r = __shfl_down_sync(0xffffffffu, em, off);
                int   a2r = __shfl_down_sync(0xffffffffu, ea, off);
                es += s2r;
                et += t2r;
                if (m2r > em || (m2r == em && a2r < ea)) ea = a2r;
                em = fmaxf(em, m2r);
            }
            if (tid == 0) {
                float lse = logf(es);
                bool valid = (lab != IGNORE_IDX);
                float per = lse - (1.0f - EPS_SMOOTH) * xl - EPS_SMOOTH * (et / (float)VV);
                g_per_tok[row] = valid ? per : 0.f;
                g_valid[row]   = valid ? 1.f : 0.f;
                g_pred[row]    = ea;
            }
        }
    }

    // ---------------- grid barrier ----------------
    __threadfence();
    __syncthreads();
    if (tid == 0) atomicAdd(&g_arrive, 1);

    if (bid >= RB_BLOCKS) return;

    if (tid == 0) {
        while (ld_acquire(&g_arrive) < GRID) __nanosleep(64);
    }
    __syncthreads();
    __threadfence();

    // ---------------- Phase B: rep loss ----------------
    const int b  = bid >> 3;
    const int sl = bid & 7;
    const int il = tid >> 3;
    const int ch = tid & 7;
    const int i  = sl * ILOC + il;

    __shared__ int   sp[SS];
    __shared__ float sv[SS];
    __shared__ float red1[16], red2[16], red3[16], red4[16];

    {
        int row = b * SS + tid;
        sp[tid] = g_pred[row];
        sv[tid] = g_valid[row];
    }
    __syncthreads();

    float total = sv[tid];
    #pragma unroll
    for (int off = 16; off; off >>= 1) total += __shfl_down_sync(0xffffffffu, total, off);
    if ((tid & 31) == 0) red1[tid >> 5] = total;
    __syncthreads();
    if (tid < 16) {
        float xx = red1[tid];
        #pragma unroll
        for (int off = 8; off; off >>= 1) xx += __shfl_down_sync(0xffffu, xx, off);
        if (tid == 0) red1[0] = xx;
    }
    __syncthreads();
    total = red1[0];
    __syncthreads();

    int   p  = sp[i];
    float vi = sv[i];
    float c = 0.f;
    int lt = 0;
    #pragma unroll 8
    for (int jj = 0; jj < JLEN; jj++) {
        int j = ch + (jj << 3);
        bool match = (sp[j] == p) && (sv[j] > 0.f);
        c += match ? 1.f : 0.f;
        lt |= (match && (j < i)) ? 1 : 0;
    }
    #pragma unroll
    for (int off = 1; off < 8; off <<= 1) {
        c  += __shfl_xor_sync(0xffffffffu, c,  off);
        lt |= __shfl_xor_sync(0xffffffffu, lt, off);
    }

    float ent = 0.f, nu = 0.f, pts = 0.f, vls = 0.f;
    if (ch == 0) {
        bool first = (vi > 0.f) && !lt;
        if (first) {
            float pr = c / fmaxf(total, 1.f);
            ent = -pr * logf(pr + 1e-10f);
            nu  = 1.f;
        }
        int row = b * SS + i;
        pts = g_per_tok[row];
        vls = vi;
    }

    #pragma unroll
    for (int off = 16; off; off >>= 1) {
        ent += __shfl_down_sync(0xffffffffu, ent, off);
        nu  += __shfl_down_sync(0xffffffffu, nu,  off);
        pts += __shfl_down_sync(0xffffffffu, pts, off);
        vls += __shfl_down_sync(0xffffffffu, vls, off);
    }
    if ((tid & 31) == 0) { red1[tid >> 5] = ent; red2[tid >> 5] = nu; red3[tid >> 5] = pts; red4[tid >> 5] = vls; }
    __syncthreads();
    if (tid < 16) {
        float e = red1[tid], n = red2[tid], q = red3[tid], w = red4[tid];
        #pragma unroll
        for (int off = 8; off; off >>= 1) {
            e += __shfl_down_sync(0xffffu, e, off);
            n += __shfl_down_sync(0xffffu, n, off);
            q += __shfl_down_sync(0xffffu, q, off);
            w += __shfl_down_sync(0xffffu, w, off);
        }
        if (tid == 0) {
            g_ent_part[bid] = e;
            g_nu_part[bid]  = n;
            g_pt_part[bid]  = q;
            g_v_part[bid]   = w;
            if (sl == 0) g_tot_b[b] = total;
        }
    }
    __syncthreads();

    if (tid == 0) {
        __threadfence();
        int old = atomicAdd(&g_arrive2, 1);
        if (old == RB_BLOCKS - 1) {
            __threadfence();
            float rep = 0.f;
            #pragma unroll
            for (int bb = 0; bb < BB; bb++) {
                float eb = 0.f, nb = 0.f;
                #pragma unroll
                for (int ss2 = 0; ss2 < SLICES; ss2++) {
                    eb += g_ent_part[bb * SLICES + ss2];
                    nb += g_nu_part[bb * SLICES + ss2];
                }
                float tb2 = g_tot_b[bb];
                rep += (tb2 > 0.f) ? (1.f - eb / logf(nb + 1.f)) : 0.f;
            }
            rep /= (float)BB;
            float cen = 0.f, ced = 0.f;
            #pragma unroll
            for (int jq = 0; jq < RB_BLOCKS; jq++) {
                cen += g_pt_part[jq];
                ced += g_v_part[jq];
            }
            float ce = cen / fmaxf(ced, 1.f);
            float tot = ce + REP_W * rep;
            out[0] = tot;
            if (out_size > 1) out[1] = ce;
            if (out_size > 2) out[2] = rep;
            g_arrive  = 0;
            g_arrive2 = 0;
        }
    }
}

extern "C" void kernel_launch(void* const* d_in, const int* in_sizes, int n_in,
                              void* d_out, int out_size) {
    const float* logits = (const float*)d_in[0];
    const void*  labels = d_in[1];

    fused_kernel<<<GRID, RK_THREADS>>>(logits, labels, (float*)d_out, out_size);
}